// round 1
// baseline (speedup 1.0000x reference)
#include <cuda_runtime.h>
#include <cuda_bf16.h>

#define DOF     300000
#define NB      8
#define TPB     512
#define NWARP   (TPB/32)
#define EPT     16
#define NEWTON  6
#define CGI     20
#define BETAC   0.1f
#define MAXSLOT 256

// ---- persistent device scratch (no allocations allowed) ----
__device__ float g_free[DOF];                 // 0/1 mask
__device__ float g_acc[MAXSLOT][NB][8];       // reduction accumulators (one slot per barrier)
__device__ int   g_cnt[NB];                   // per-batch barrier counters

// ---- init kernels (run each replay inside the graph) ----
__global__ void k_init()
{
    int i = blockIdx.x * blockDim.x + threadIdx.x;
    if (i < MAXSLOT * NB * 8) ((float*)g_acc)[i] = 0.f;
    if (i < NB) g_cnt[i] = 0;
    if (i < DOF) g_free[i] = 1.f;
}

__global__ void k_fix(const int* __restrict__ fixed, int nfixed)
{
    int i = blockIdx.x * blockDim.x + threadIdx.x;
    if (i < nfixed) {
        int d = fixed[i];
        if (d >= 0 && d < DOF) g_free[d] = 0.f;
    }
}

// ---- reduction helpers ----
__device__ __forceinline__ float warp_red(float v)
{
#pragma unroll
    for (int o = 16; o; o >>= 1) v += __shfl_down_sync(0xffffffffu, v, o);
    return v;
}

// Single-value block reduce + cross-block (per-batch) barrier + broadcast.
// slot must be a globally consistent, monotonically increasing index (same on
// every block of the batch). Returns the batch-wide sum to every thread.
__device__ __forceinline__ float red_sync(float part, int batch, int bpb, int slot,
                                          float (*s_w)[8], float* s_bc, int tid)
{
    int lane = tid & 31, wid = tid >> 5;
    float w = warp_red(part);
    if (lane == 0) s_w[wid][0] = w;
    __syncthreads();
    if (tid == 0) {
        float s = 0.f;
#pragma unroll
        for (int j = 0; j < NWARP; j++) s += s_w[j][0];
        atomicAdd(&g_acc[slot][batch][0], s);
        __threadfence();
        atomicAdd(&g_cnt[batch], 1);
        int tgt = (slot + 1) * bpb;
        while (*((volatile int*)&g_cnt[batch]) < tgt) __nanosleep(32);
        __threadfence();
        s_bc[0] = __ldcg(&g_acc[slot][batch][0]);
    }
    __syncthreads();
    return s_bc[0];
}

// ---- persistent solver: one launch does all 6 Newton steps ----
__global__ void __launch_bounds__(TPB, 2)
k_solver(const float* __restrict__ F, const float* __restrict__ U0,
         const float* __restrict__ Kd, float* __restrict__ OUT, int bpb)
{
    extern __shared__ float sh[];
    float* u_s = sh;               // EPT*TPB floats
    float* x_s = sh + EPT * TPB;   // EPT*TPB floats
    __shared__ float s_w[NWARP][8];
    __shared__ float s_bc[8];

    const int tid    = threadIdx.x;
    const int lane   = tid & 31;
    const int wid    = tid >> 5;
    const int batch  = blockIdx.x / bpb;
    const int blk    = blockIdx.x - batch * bpb;
    const int base   = blk * TPB + tid;
    const int stride = bpb * TPB;
    const float* __restrict__ f = F + batch * DOF;

    const float alphas[8] = {1.f, 0.5f, 0.25f, 0.125f, 0.0625f, 0.05f, 0.05f, 0.05f};

    // load u0 into shared (u stays on-chip for the whole solve)
#pragma unroll
    for (int i = 0; i < EPT; i++) {
        int d = base + i * stride;
        u_s[i * TPB + tid] = (d < DOF) ? U0[batch * DOF + d] : 0.f;
    }

    float r[EPT], p[EPT], hm[EPT];
    int slot = 0;
    float rns = 0.f, init2 = 0.f;

    for (int nit = 0; nit < NEWTON; ++nit) {
        // ---- Newton boundary: residual, CG init, Hessian diagonal ----
        float part = 0.f;
#pragma unroll
        for (int i = 0; i < EPT; i++) {
            int d = base + i * stride;
            float rv = 0.f, hv = 0.f;
            if (d < DOF) {
                float k  = Kd[d];
                float fr = g_free[d];
                float u  = u_s[i * TPB + tid];
                float fv = f[d];
                float filt = fr * (fv - (k * u + 4.f * BETAC * u * u * u));
                rv = -filt;                                 // b = -filtered, r0 = b
                hv = fr * (k + 12.f * BETAC * u * u);       // masked Hessian diag
                part += filt * filt;
            }
            r[i] = rv; p[i] = rv; hm[i] = hv;
            x_s[i * TPB + tid] = 0.f;
        }
        rns   = red_sync(part, batch, bpb, slot++, s_w, s_bc, tid);
        init2 = rns;  // ||filtered||^2

        // ---- CG (A is the masked diagonal; p,r,x stay masked) ----
        for (int it = 0; it < CGI; ++it) {
            part = 0.f;
#pragma unroll
            for (int i = 0; i < EPT; i++) part += p[i] * (hm[i] * p[i]);
            float pAp = red_sync(part, batch, bpb, slot++, s_w, s_bc, tid);

            float alpha = (fabsf(pAp) > 0.f) ? (rns / pAp) : 0.f;

            part = 0.f;
#pragma unroll
            for (int i = 0; i < EPT; i++) {
                float Ap = hm[i] * p[i];
                x_s[i * TPB + tid] += alpha * p[i];
                r[i] -= alpha * Ap;
                part += r[i] * r[i];
            }
            float nrns = red_sync(part, batch, bpb, slot++, s_w, s_bc, tid);

            float beta = (rns > 0.f) ? (nrns / rns) : 0.f;
#pragma unroll
            for (int i = 0; i < EPT; i++) p[i] = r[i] + beta * p[i];
            rns = nrns;
        }

        // ---- line search: 8 trial residual norms in one pass ----
        float acc[8];
#pragma unroll
        for (int t = 0; t < 8; t++) acc[t] = 0.f;
#pragma unroll
        for (int i = 0; i < EPT; i++) {
            int d = base + i * stride;
            if (d < DOF) {
                float k  = Kd[d];
                float fr = g_free[d];
                float u  = u_s[i * TPB + tid];
                float du = x_s[i * TPB + tid];
                float fv = f[d];
#pragma unroll
                for (int t = 0; t < 8; t++) {
                    float c   = u + alphas[t] * du;
                    float res = fr * (fv - (k * c + 4.f * BETAC * c * c * c));
                    acc[t] += res * res;
                }
            }
        }
        // 8-value reduce + barrier + broadcast
        {
#pragma unroll
            for (int t = 0; t < 8; t++) acc[t] = warp_red(acc[t]);
            if (lane == 0) {
#pragma unroll
                for (int t = 0; t < 8; t++) s_w[wid][t] = acc[t];
            }
            __syncthreads();
            if (tid == 0) {
#pragma unroll
                for (int t = 0; t < 8; t++) {
                    float s = 0.f;
#pragma unroll
                    for (int j = 0; j < NWARP; j++) s += s_w[j][t];
                    atomicAdd(&g_acc[slot][batch][t], s);
                }
                __threadfence();
                atomicAdd(&g_cnt[batch], 1);
                int tgt = (slot + 1) * bpb;
                while (*((volatile int*)&g_cnt[batch]) < tgt) __nanosleep(32);
                __threadfence();
#pragma unroll
                for (int t = 0; t < 8; t++) s_bc[t] = __ldcg(&g_acc[slot][batch][t]);
            }
            __syncthreads();
            slot++;
        }

        // first alpha (smallest t) whose squared norm improves; else ALPHA_MIN
        float ab = 0.05f;
#pragma unroll
        for (int t = 7; t >= 0; t--)
            if (s_bc[t] < init2) ab = alphas[t];

        // u += alpha_b * du  (du = x, already masked)
#pragma unroll
        for (int i = 0; i < EPT; i++)
            u_s[i * TPB + tid] += ab * x_s[i * TPB + tid];
    }

    // write final u
#pragma unroll
    for (int i = 0; i < EPT; i++) {
        int d = base + i * stride;
        if (d < DOF) OUT[batch * DOF + d] = u_s[i * TPB + tid];
    }
}

extern "C" void kernel_launch(void* const* d_in, const int* in_sizes, int n_in,
                              void* d_out, int out_size)
{
    const float* F     = (const float*)d_in[0];
    const float* U0    = (const float*)d_in[1];
    const float* Kd    = (const float*)d_in[2];
    const int*   fixed = (const int*)d_in[3];
    int nfixed = in_sizes[3];
    float* out = (float*)d_out;

    int dev = 0;
    cudaGetDevice(&dev);
    int sm = 148;
    cudaDeviceGetAttribute(&sm, cudaDevAttrMultiProcessorCount, dev);

    // exactly 2 CTAs/SM so every block is co-resident (software barrier safety)
    int bpb = (2 * sm) / NB;
    int need = (DOF + TPB * EPT - 1) / (TPB * EPT);  // 37
    if (bpb < need) bpb = need;

    size_t shmem = (size_t)2 * EPT * TPB * sizeof(float);  // 64 KB
    cudaFuncSetAttribute(k_solver, cudaFuncAttributeMaxDynamicSharedMemorySize, (int)shmem);

    k_init<<<(DOF + 255) / 256, 256>>>();
    k_fix<<<(nfixed + 255) / 256, 256>>>(fixed, nfixed);
    k_solver<<<bpb * NB, TPB, shmem>>>(F, U0, Kd, out, bpb);
}

// round 3
// speedup vs baseline: 10.8268x; 10.8268x over previous
#include <cuda_runtime.h>
#include <cuda_bf16.h>

#define DOF     300000
#define E4      (DOF/4)        // 75000 float4
#define NB      8
#define TPB     256
#define NWARP   (TPB/32)
#define NCHUNK  8              // float4 per thread
#define NEWTON  6
#define BETAC   0.1f
#define NRED    9              // 1 init norm + 8 candidate norms
#define MAXSLOT 8
#define BPBMAX  64

// ---- persistent device scratch (no allocations allowed) ----
__device__ float g_kf[DOF];               // free * k_diag (0 iff fixed)
__device__ float g_acc[MAXSLOT][NB][16];  // reduction accumulators
__device__ int   g_cnt[NB];               // per-batch barrier counters

// ---- init kernels (re-run on every graph replay) ----
__global__ void k_init(const float* __restrict__ Kd)
{
    int i = blockIdx.x * blockDim.x + threadIdx.x;
    if (i < MAXSLOT * NB * 16) ((float*)g_acc)[i] = 0.f;
    if (i < NB) g_cnt[i] = 0;
    if (i < E4) ((float4*)g_kf)[i] = ((const float4*)Kd)[i];
}

__global__ void k_fix(const int* __restrict__ fixed, int nfixed)
{
    int i = blockIdx.x * blockDim.x + threadIdx.x;
    if (i < nfixed) {
        int d = fixed[i];
        if (d >= 0 && d < DOF) g_kf[d] = 0.f;
    }
}

__device__ __forceinline__ float warp_red(float v)
{
#pragma unroll
    for (int o = 16; o; o >>= 1) v += __shfl_down_sync(0xffffffffu, v, o);
    return v;
}

// ---- proven R1-style barrier: 9-value reduce across the batch's blocks ----
__device__ __forceinline__ void bar9(float* acc, int batch, int blk, int bpb, int slot,
                                     float (*s_w)[NRED], float* s_bc, int tid)
{
    int lane = tid & 31, wid = tid >> 5;
#pragma unroll
    for (int k = 0; k < NRED; k++) acc[k] = warp_red(acc[k]);
    if (lane == 0) {
#pragma unroll
        for (int k = 0; k < NRED; k++) s_w[wid][k] = acc[k];
    }
    __syncthreads();
    if (tid == 0) {
#pragma unroll
        for (int k = 0; k < NRED; k++) {
            float s = 0.f;
#pragma unroll
            for (int j = 0; j < NWARP; j++) s += s_w[j][k];
            atomicAdd(&g_acc[slot][batch][k], s);
        }
        __threadfence();
        atomicAdd(&g_cnt[batch], 1);
        int tgt = (slot + 1) * bpb;
        while (*((volatile int*)&g_cnt[batch]) < tgt) __nanosleep(64);
        __threadfence();
#pragma unroll
        for (int k = 0; k < NRED; k++) s_bc[k] = __ldcg(&g_acc[slot][batch][k]);
    }
    __syncthreads();
}

// ---- persistent solver: u, du in registers; 1 barrier per Newton step ----
__global__ void __launch_bounds__(TPB, 2)
k_solver(const float* __restrict__ F, const float* __restrict__ U0,
         float* __restrict__ OUT, int bpb)
{
    __shared__ float s_w[NWARP][NRED];
    __shared__ float s_bc[NRED];

    const int tid   = threadIdx.x;
    const int batch = blockIdx.x / bpb;
    const int blk   = blockIdx.x - batch * bpb;
    const int base  = blk * TPB + tid;
    const int grp   = bpb * TPB;

    const float4* __restrict__ kf4 = (const float4*)g_kf;
    const float4* __restrict__ f4  = ((const float4*)F) + batch * E4;
    const float4* __restrict__ u04 = ((const float4*)U0) + batch * E4;

    const float al[8] = {1.f, 0.5f, 0.25f, 0.125f, 0.0625f, 0.05f, 0.05f, 0.05f};
    const float4 z4 = make_float4(0.f, 0.f, 0.f, 0.f);

    float4 u[NCHUNK], du[NCHUNK];

    // load u0 (registers for the whole solve)
#pragma unroll
    for (int c = 0; c < NCHUNK; c++) {
        int e = c * grp + base;
        u[c] = (e < E4) ? __ldg(u04 + e) : z4;
    }

    for (int nit = 0; nit < NEWTON; ++nit) {
        float acc[NRED];
#pragma unroll
        for (int k = 0; k < NRED; k++) acc[k] = 0.f;

#pragma unroll
        for (int c = 0; c < NCHUNK; c++) {
            int e = c * grp + base;
            float4 D = z4;
            if (e < E4) {
                float4 kf = __ldg(kf4 + e);
                float4 fv = __ldg(f4 + e);
#pragma unroll
                for (int comp = 0; comp < 4; comp++) {
                    float kfc = (&kf.x)[comp];
                    float fvc = (&fv.x)[comp];
                    float uu  = (&u[c].x)[comp];
                    float fr  = (kfc > 0.f) ? 1.f : 0.f;
                    float bf  = (4.f * BETAC) * fr;           // masked 4*beta
                    float u2  = uu * uu;
                    // filtered residual: fr*(f - k u - 4b u^3)
                    float filt = fr * fvc - fmaf(kfc, uu, bf * u2 * uu);
                    acc[0] = fmaf(filt, filt, acc[0]);
                    // diagonal Hessian (guarded for division on fixed dofs)
                    float hden = (kfc > 0.f) ? fmaf(12.f * BETAC, u2, kfc) : 1.f;
                    // exact CG limit: du = b/h with b = -filtered
                    float d = -filt / hden;
                    (&D.x)[comp] = d;
                    // res(alpha) = A + B a + C a^2 + Dd a^3 (cubic in alpha)
                    float A  = filt;
                    float B  = -fmaf(3.f * bf * u2, d, kfc * d);
                    float C  = -3.f * bf * uu * d * d;
                    float Dd = -bf * d * d * d;
#pragma unroll
                    for (int t = 0; t < 8; t++) {
                        float a   = al[t];
                        float res = fmaf(a, fmaf(a, fmaf(a, Dd, C), B), A);
                        acc[1 + t] = fmaf(res, res, acc[1 + t]);
                    }
                }
            }
            du[c] = D;
        }

        bar9(acc, batch, blk, bpb, nit, s_w, s_bc, tid);

        // first improving alpha (smallest t); default ALPHA_MIN
        float init2 = s_bc[0];
        float ab = 0.05f;
#pragma unroll
        for (int t = 7; t >= 0; t--)
            if (s_bc[1 + t] < init2) ab = al[t];

        // u += alpha * du   (du = 0 on fixed / out-of-range)
#pragma unroll
        for (int c = 0; c < NCHUNK; c++) {
            u[c].x = fmaf(ab, du[c].x, u[c].x);
            u[c].y = fmaf(ab, du[c].y, u[c].y);
            u[c].z = fmaf(ab, du[c].z, u[c].z);
            u[c].w = fmaf(ab, du[c].w, u[c].w);
        }
    }

    // write final u
#pragma unroll
    for (int c = 0; c < NCHUNK; c++) {
        int e = c * grp + base;
        if (e < E4) ((float4*)OUT)[batch * E4 + e] = u[c];
    }
}

extern "C" void kernel_launch(void* const* d_in, const int* in_sizes, int n_in,
                              void* d_out, int out_size)
{
    const float* F     = (const float*)d_in[0];
    const float* U0    = (const float*)d_in[1];
    const float* Kd    = (const float*)d_in[2];
    const int*   fixed = (const int*)d_in[3];
    int nfixed = in_sizes[3];
    float* out = (float*)d_out;

    int dev = 0;
    cudaGetDevice(&dev);
    int sm = 148;
    cudaDeviceGetAttribute(&sm, cudaDevAttrMultiProcessorCount, dev);

    int bpb = (2 * sm) / NB;                                  // 2 CTAs/SM, co-resident
    int need = (E4 + TPB * NCHUNK - 1) / (TPB * NCHUNK);      // 37
    if (bpb < need) bpb = need;
    if (bpb > BPBMAX) bpb = BPBMAX;

    k_init<<<(E4 + 255) / 256, 256>>>(Kd);
    k_fix<<<(nfixed + 255) / 256, 256>>>(fixed, nfixed);
    k_solver<<<bpb * NB, TPB>>>(F, U0, out, bpb);
}

// round 6
// speedup vs baseline: 18.1894x; 1.6800x over previous
#include <cuda_runtime.h>
#include <cuda_bf16.h>

#define DOF     300000
#define E4      75000          // DOF/4 float4 elements
#define NB      8
#define TPB     256
#define NWARP   (TPB/32)
#define NCHUNK  8              // float4 per thread
#define NEWTON  6
#define MWORDS  ((DOF + 31) / 32)   // 9375 mask words
#define NRED    6              // P0..P5 elementwise sums
#define BPBMAX  64

// ---- persistent device scratch (no allocations allowed) ----
__device__ unsigned g_mask[MWORDS];          // bit = 1 -> fixed dof
__device__ float    g_acc[NEWTON][NB][8];    // reduction accumulators
__device__ int      g_cnt[NB];               // per-batch barrier counters

// ---- tiny init kernels (re-run on each graph replay) ----
__global__ void k_zero()
{
    int i = blockIdx.x * blockDim.x + threadIdx.x;
    if (i < MWORDS) g_mask[i] = 0u;
    if (i < NEWTON * NB * 8) ((float*)g_acc)[i] = 0.f;
    if (i < NB) g_cnt[i] = 0;
}

__global__ void k_fix(const int* __restrict__ fixed, int nfixed)
{
    int i = blockIdx.x * blockDim.x + threadIdx.x;
    if (i < nfixed) {
        int d = fixed[i];
        if (d >= 0 && d < DOF) atomicOr(&g_mask[d >> 5], 1u << (d & 31));
    }
}

__device__ __forceinline__ float warp_red(float v)
{
#pragma unroll
    for (int o = 16; o; o >>= 1) v += __shfl_down_sync(0xffffffffu, v, o);
    return v;
}

__device__ __forceinline__ float frcp(float x)
{
    float r;
    asm("rcp.approx.ftz.f32 %0, %1;" : "=f"(r) : "f"(x));
    return r;
}

// ---- proven R1/R3 barrier: NRED-value reduce across the batch's blocks ----
__device__ __forceinline__ void bar6(float* acc, int batch, int blk, int bpb, int slot,
                                     float (*s_w)[NRED], float* s_bc, int tid)
{
    int lane = tid & 31, wid = tid >> 5;
#pragma unroll
    for (int k = 0; k < NRED; k++) acc[k] = warp_red(acc[k]);
    if (lane == 0) {
#pragma unroll
        for (int k = 0; k < NRED; k++) s_w[wid][k] = acc[k];
    }
    __syncthreads();
    if (tid == 0) {
#pragma unroll
        for (int k = 0; k < NRED; k++) {
            float s = 0.f;
#pragma unroll
            for (int j = 0; j < NWARP; j++) s += s_w[j][k];
            atomicAdd(&g_acc[slot][batch][k], s);
        }
        __threadfence();
        atomicAdd(&g_cnt[batch], 1);
        int tgt = (slot + 1) * bpb;
        while (*((volatile int*)&g_cnt[batch]) < tgt) __nanosleep(64);
        __threadfence();
#pragma unroll
        for (int k = 0; k < NRED; k++) s_bc[k] = __ldcg(&g_acc[slot][batch][k]);
    }
    __syncthreads();
}

// ---- persistent solver ----
__global__ void __launch_bounds__(TPB, 2)
k_solver(const float* __restrict__ F, const float* __restrict__ U0,
         const float* __restrict__ Kd, float* __restrict__ OUT, int bpb)
{
    extern __shared__ float4 sh4[];
    float4* s_kf = sh4;                    // masked k (0 iff fixed/OOB)
    float4* s_f  = sh4 + NCHUNK * TPB;     // raw f
    __shared__ float s_w[NWARP][NRED];
    __shared__ float s_bc[NRED];

    const int tid   = threadIdx.x;
    const int batch = blockIdx.x / bpb;
    const int blk   = blockIdx.x - batch * bpb;
    const int base  = blk * TPB + tid;
    const int grp   = bpb * TPB;

    const float4* __restrict__ kd4 = (const float4*)Kd;
    const float4* __restrict__ f4  = ((const float4*)F) + batch * E4;
    const float4* __restrict__ u04 = ((const float4*)U0) + batch * E4;

    // 6 distinct alphas (trials 5..7 are all 0.05)
    const float al[6] = {1.f, 0.5f, 0.25f, 0.125f, 0.0625f, 0.05f};
    const float4 z4 = make_float4(0.f, 0.f, 0.f, 0.f);

    float4 u[NCHUNK], du[NCHUNK];

    // ---- one-time load: u0 -> regs, masked Kd + f -> smem ----
#pragma unroll
    for (int c = 0; c < NCHUNK; c++) {
        int e = c * grp + base;
        float4 U = z4, KF = z4, FV = z4;
        if (e < E4) {
            float4 kd = __ldg(kd4 + e);
            FV = __ldg(f4 + e);
            U  = __ldg(u04 + e);
            unsigned w   = __ldg(&g_mask[e >> 3]);
            unsigned nib = (w >> (4 * (e & 7))) & 0xFu;
            KF.x = (nib & 1u) ? 0.f : kd.x;
            KF.y = (nib & 2u) ? 0.f : kd.y;
            KF.z = (nib & 4u) ? 0.f : kd.z;
            KF.w = (nib & 8u) ? 0.f : kd.w;
        }
        s_kf[c * TPB + tid] = KF;
        s_f [c * TPB + tid] = FV;
        u[c] = U;
    }
    __syncthreads();

    for (int nit = 0; nit < NEWTON; ++nit) {
        // P0=SumA^2 P1=SumAC P2=SumAD P3=SumC^2 P4=SumCD P5=SumD^2
        float acc[NRED];
#pragma unroll
        for (int k = 0; k < NRED; k++) acc[k] = 0.f;

#pragma unroll
        for (int c = 0; c < NCHUNK; c++) {
            float4 kf = s_kf[c * TPB + tid];
            float4 fv = s_f [c * TPB + tid];
            float4 D4;
#pragma unroll
            for (int comp = 0; comp < 4; comp++) {
                float kfc = (&kf.x)[comp];
                float fvc = (&fv.x)[comp];
                float uu  = (&u[c].x)[comp];
                bool  fr  = (kfc > 0.f);
                float u2  = uu * uu;
                float cub = (0.4f * u2) * uu;                 // 4*beta*u^3
                float g   = fvc - fmaf(kfc, uu, cub);
                float A   = fr ? g : 0.f;                     // filtered residual
                float h   = fmaf(1.2f, u2, kfc);              // k + 12*beta*u^2
                float hs  = fr ? h : 1.f;
                float d   = -A * frcp(hs);                    // exact CG limit
                float d2  = d * d;
                float C   = (-1.2f * uu) * d2;                // -12*beta*u*d^2
                float Dd  = (-0.4f * d2) * d;                 // -4*beta*d^3
                (&D4.x)[comp] = d;
                acc[0] = fmaf(A,  A,  acc[0]);
                acc[1] = fmaf(A,  C,  acc[1]);
                acc[2] = fmaf(A,  Dd, acc[2]);
                acc[3] = fmaf(C,  C,  acc[3]);
                acc[4] = fmaf(C,  Dd, acc[4]);
                acc[5] = fmaf(Dd, Dd, acc[5]);
            }
            du[c] = D4;
        }

        bar6(acc, batch, blk, bpb, nit, s_w, s_bc, tid);

        // ||res(a)||^2 = S0 + S1 a + ... + S6 a^6  (B == A identity)
        float P0 = s_bc[0], P1 = s_bc[1], P2 = s_bc[2];
        float P3 = s_bc[3], P4 = s_bc[4], P5 = s_bc[5];
        float S0 = P0;
        float S1 = 2.f * P0;
        float S2 = fmaf(2.f, P1, P0);
        float S3 = 2.f * (P1 + P2);
        float S4 = fmaf(2.f, P2, P3);
        float S5 = 2.f * P4;
        float S6 = P5;

        // first improving alpha (smallest trial index); default ALPHA_MIN
        float ab = 0.05f;
#pragma unroll
        for (int t = 5; t >= 0; t--) {
            float a = al[t];
            float v = S6;
            v = fmaf(v, a, S5);
            v = fmaf(v, a, S4);
            v = fmaf(v, a, S3);
            v = fmaf(v, a, S2);
            v = fmaf(v, a, S1);
            v = fmaf(v, a, S0);
            if (v < S0) ab = a;
        }

        // u += alpha * du
#pragma unroll
        for (int c = 0; c < NCHUNK; c++) {
            u[c].x = fmaf(ab, du[c].x, u[c].x);
            u[c].y = fmaf(ab, du[c].y, u[c].y);
            u[c].z = fmaf(ab, du[c].z, u[c].z);
            u[c].w = fmaf(ab, du[c].w, u[c].w);
        }
    }

    // write final u
#pragma unroll
    for (int c = 0; c < NCHUNK; c++) {
        int e = c * grp + base;
        if (e < E4) ((float4*)OUT)[batch * E4 + e] = u[c];
    }
}

extern "C" void kernel_launch(void* const* d_in, const int* in_sizes, int n_in,
                              void* d_out, int out_size)
{
    const float* F     = (const float*)d_in[0];
    const float* U0    = (const float*)d_in[1];
    const float* Kd    = (const float*)d_in[2];
    const int*   fixed = (const int*)d_in[3];
    int nfixed = in_sizes[3];
    float* out = (float*)d_out;

    int dev = 0;
    cudaGetDevice(&dev);
    int sm = 148;
    cudaDeviceGetAttribute(&sm, cudaDevAttrMultiProcessorCount, dev);

    int bpb = (2 * sm) / NB;                                  // 2 CTAs/SM, co-resident
    int need = (E4 + TPB * NCHUNK - 1) / (TPB * NCHUNK);      // 37
    if (bpb < need) bpb = need;
    if (bpb > BPBMAX) bpb = BPBMAX;

    size_t shmem = (size_t)2 * NCHUNK * TPB * sizeof(float4); // 64 KB
    cudaFuncSetAttribute(k_solver, cudaFuncAttributeMaxDynamicSharedMemorySize, (int)shmem);

    k_zero<<<(MWORDS + 255) / 256, 256>>>();
    k_fix<<<(nfixed + 255) / 256, 256>>>(fixed, nfixed);
    k_solver<<<bpb * NB, TPB, shmem>>>(F, U0, Kd, out, bpb);
}

// round 8
// speedup vs baseline: 19.1881x; 1.0549x over previous
#include <cuda_runtime.h>
#include <cuda_bf16.h>

#define DOF     300000
#define E4      75000          // DOF/4 float4 elements
#define NB      8
#define TPB     256
#define NWARP   (TPB/32)
#define NCHUNK  8              // float4 per thread
#define NEWTON  6
#define NRED    6
#define BPBMAX  64

// ---- persistent device scratch (self-resetting across graph replays) ----
// Invariant at every kernel-launch boundary: for all slots except the last-used
// one (slot 5), g_scnt==0 and g_acc==0; slot 5 is reset at slot 0 of the next run.
__device__ float g_acc[NEWTON][NB][8];   // zero-initialized at load
__device__ int   g_scnt[NEWTON][NB];     // zero-initialized at load

__device__ __forceinline__ float warp_red(float v)
{
#pragma unroll
    for (int o = 16; o; o >>= 1) v += __shfl_down_sync(0xffffffffu, v, o);
    return v;
}

__device__ __forceinline__ float frcp(float x)
{
    float r;
    asm("rcp.approx.ftz.f32 %0, %1;" : "=f"(r) : "f"(x));
    return r;
}

// ---- proven atomic barrier, per-slot counter, self-resetting ----
__device__ __forceinline__ void bar6(float* acc, int batch, int blk, int bpb, int slot,
                                     float (*s_w)[NRED], float* s_bc, int tid)
{
    int lane = tid & 31, wid = tid >> 5;
#pragma unroll
    for (int k = 0; k < NRED; k++) acc[k] = warp_red(acc[k]);
    if (lane == 0) {
#pragma unroll
        for (int k = 0; k < NRED; k++) s_w[wid][k] = acc[k];
    }
    __syncthreads();
    if (tid == 0) {
#pragma unroll
        for (int k = 0; k < NRED; k++) {
            float s = 0.f;
#pragma unroll
            for (int j = 0; j < NWARP; j++) s += s_w[j][k];
            atomicAdd(&g_acc[slot][batch][k], s);
        }
        __threadfence();
        atomicAdd(&g_scnt[slot][batch], 1);
        while (*((volatile int*)&g_scnt[slot][batch]) < bpb) __nanosleep(64);
        __threadfence();
#pragma unroll
        for (int k = 0; k < NRED; k++) s_bc[k] = __ldcg(&g_acc[slot][batch][k]);

        // Reset the PREVIOUS slot (blk 0 only). Safe: counter[slot]==bpb implies
        // every block passed slot-1's spin and will not touch it again this run;
        // next use of slot-1 (next replay, or slot 5 later this run when slot==0)
        // is ordered after blk0's subsequent fenced counter increments.
        if (blk == 0) {
            int prev = (slot + NEWTON - 1) % NEWTON;
#pragma unroll
            for (int k = 0; k < NRED; k++) g_acc[prev][batch][k] = 0.f;
            __threadfence();
            atomicExch(&g_scnt[prev][batch], 0);
        }
    }
    __syncthreads();
}

// ---- single persistent kernel: init + fixed-dof patch + 6 Newton steps ----
__global__ void __launch_bounds__(TPB, 2)
k_solver(const float* __restrict__ F, const float* __restrict__ U0,
         const float* __restrict__ Kd, const int* __restrict__ fixed,
         int nfixed, float* __restrict__ OUT, int bpb)
{
    extern __shared__ float4 sh4[];
    float4* s_kf = sh4;                    // Kd with fixed dofs zeroed
    float4* s_f  = sh4 + NCHUNK * TPB;     // raw f
    __shared__ float s_w[NWARP][NRED];
    __shared__ float s_bc[NRED];

    const int tid   = threadIdx.x;
    const int batch = blockIdx.x / bpb;
    const int blk   = blockIdx.x - batch * bpb;
    const int base  = blk * TPB + tid;
    const int grp   = bpb * TPB;

    const float4* __restrict__ kd4 = (const float4*)Kd;
    const float4* __restrict__ f4  = ((const float4*)F) + batch * E4;
    const float4* __restrict__ u04 = ((const float4*)U0) + batch * E4;

    const float al[6] = {1.f, 0.5f, 0.25f, 0.125f, 0.0625f, 0.05f};
    const float4 z4 = make_float4(0.f, 0.f, 0.f, 0.f);

    float4 u[NCHUNK], du[NCHUNK];

    // ---- one-time load: u0 -> regs, Kd + f -> smem ----
#pragma unroll
    for (int c = 0; c < NCHUNK; c++) {
        int e = c * grp + base;
        float4 U = z4, KF = z4, FV = z4;
        if (e < E4) {
            KF = __ldg(kd4 + e);
            FV = __ldg(f4 + e);
            U  = __ldg(u04 + e);
        }
        s_kf[c * TPB + tid] = KF;
        s_f [c * TPB + tid] = FV;
        u[c] = U;
    }
    __syncthreads();

    // ---- patch fixed dofs: zero owned s_kf scalars (kfc==0 <=> fixed/OOB) ----
    for (int i = tid; i < nfixed; i += TPB) {
        int dd = __ldg(fixed + i);
        if (dd >= 0 && dd < DOF) {
            int e = dd >> 2, comp = dd & 3;
            int c = e / grp;
            int o = e - c * grp;
            if ((o / TPB) == blk)
                ((float*)&s_kf[c * TPB + (o % TPB)])[comp] = 0.f;
        }
    }
    __syncthreads();

    for (int nit = 0; nit < NEWTON; ++nit) {
        // moments: M0=SumA^2 M1=SumA*w M2=SumA*v M3=Sumw^2 M4=Sumw*v M5=Sumv^2
        // with w = u*d^2, v = d^3
        float acc[NRED];
#pragma unroll
        for (int k = 0; k < NRED; k++) acc[k] = 0.f;

#pragma unroll
        for (int c = 0; c < NCHUNK; c++) {
            float4 kf = s_kf[c * TPB + tid];
            float4 fv = s_f [c * TPB + tid];
            float4 D4;
#pragma unroll
            for (int comp = 0; comp < 4; comp++) {
                float kfc = (&kf.x)[comp];
                float fvc = (&fv.x)[comp];
                float uu  = (&u[c].x)[comp];
                bool  fr  = (kfc > 0.f);
                float u2  = uu * uu;
                float t04 = 0.4f * u2;                        // 4*beta*u^2
                float g   = fmaf(-kfc, uu, fvc);
                g         = fmaf(-t04, uu, g);                // f - k u - 4b u^3
                float A   = fr ? g : 0.f;                     // filtered residual
                float h   = fmaf(1.2f, u2, kfc);              // k + 12b u^2
                float hs  = fr ? h : 1.f;
                float d   = -A * frcp(hs);                    // exact CG limit
                float d2  = d * d;
                float w   = uu * d2;
                float v   = d2 * d;
                (&D4.x)[comp] = d;
                acc[0] = fmaf(A, A, acc[0]);
                acc[1] = fmaf(A, w, acc[1]);
                acc[2] = fmaf(A, v, acc[2]);
                acc[3] = fmaf(w, w, acc[3]);
                acc[4] = fmaf(w, v, acc[4]);
                acc[5] = fmaf(v, v, acc[5]);
            }
            du[c] = D4;
        }

        bar6(acc, batch, blk, bpb, nit, s_w, s_bc, tid);

        // P-terms with constants folded in scalar-side
        float P0 = s_bc[0];
        float P1 = -1.2f  * s_bc[1];   // Sum A*C,  C = -1.2 w
        float P2 = -0.4f  * s_bc[2];   // Sum A*D,  D = -0.4 v
        float P3 =  1.44f * s_bc[3];   // Sum C^2
        float P4 =  0.48f * s_bc[4];   // Sum C*D
        float P5 =  0.16f * s_bc[5];   // Sum D^2

        // ||res(a)||^2 = S0 + S1 a + ... + S6 a^6   (B == A identity)
        float S0 = P0;
        float S1 = 2.f * P0;
        float S2 = fmaf(2.f, P1, P0);
        float S3 = 2.f * (P1 + P2);
        float S4 = fmaf(2.f, P2, P3);
        float S5 = 2.f * P4;
        float S6 = P5;

        // first improving alpha (smallest trial index); default ALPHA_MIN
        float ab = 0.05f;
#pragma unroll
        for (int t = 5; t >= 0; t--) {
            float a = al[t];
            float vv = S6;
            vv = fmaf(vv, a, S5);
            vv = fmaf(vv, a, S4);
            vv = fmaf(vv, a, S3);
            vv = fmaf(vv, a, S2);
            vv = fmaf(vv, a, S1);
            vv = fmaf(vv, a, S0);
            if (vv < S0) ab = a;
        }

        // u += alpha * du
#pragma unroll
        for (int c = 0; c < NCHUNK; c++) {
            u[c].x = fmaf(ab, du[c].x, u[c].x);
            u[c].y = fmaf(ab, du[c].y, u[c].y);
            u[c].z = fmaf(ab, du[c].z, u[c].z);
            u[c].w = fmaf(ab, du[c].w, u[c].w);
        }
    }

    // write final u
#pragma unroll
    for (int c = 0; c < NCHUNK; c++) {
        int e = c * grp + base;
        if (e < E4) ((float4*)OUT)[batch * E4 + e] = u[c];
    }
}

extern "C" void kernel_launch(void* const* d_in, const int* in_sizes, int n_in,
                              void* d_out, int out_size)
{
    const float* F     = (const float*)d_in[0];
    const float* U0    = (const float*)d_in[1];
    const float* Kd    = (const float*)d_in[2];
    const int*   fixed = (const int*)d_in[3];
    int nfixed = in_sizes[3];
    float* out = (float*)d_out;

    int dev = 0;
    cudaGetDevice(&dev);
    int sm = 148;
    cudaDeviceGetAttribute(&sm, cudaDevAttrMultiProcessorCount, dev);

    int bpb = (2 * sm) / NB;                                  // 2 CTAs/SM, co-resident
    int need = (E4 + TPB * NCHUNK - 1) / (TPB * NCHUNK);      // 37
    if (bpb < need) bpb = need;
    if (bpb > BPBMAX) bpb = BPBMAX;

    size_t shmem = (size_t)2 * NCHUNK * TPB * sizeof(float4); // 64 KB
    cudaFuncSetAttribute(k_solver, cudaFuncAttributeMaxDynamicSharedMemorySize, (int)shmem);

    k_solver<<<bpb * NB, TPB, shmem>>>(F, U0, Kd, fixed, nfixed, out, bpb);
}